// round 11
// baseline (speedup 1.0000x reference)
#include <cuda_runtime.h>
#include <math.h>

#define N_NODES 50000
#define N_EDGES 800000
#define E_TOT   850000   // edges + self loops
#define D_IN    128
#define D_HID   64
#define N_CLS   40

#define NEG_BIG (-1.0e30f)   // finite "-inf" sentinel: exp(NEG_BIG - x) == 0, no NaN

// ---------------- scratch (static __device__ globals; no allocs) ------------
__device__ float g_h   [N_NODES * D_HID];   // GEMM output / GAT input
__device__ float g_h2  [N_NODES * D_HID];   // GAT output / next GEMM input
__device__ float g_sim [E_TOT];             // per-CSR-slot leaky-relu score
__device__ float g_as  [N_NODES];           // h . aW[:D]
__device__ float g_at  [N_NODES];           // h . aW[D:] + ab
__device__ int   g_deg [N_NODES];           // in-degree (incl self loop)
__device__ int   g_rowptr[N_NODES + 1];     // CSR row pointers (by dst)
__device__ int   g_cursor[N_NODES];         // scatter cursors
__device__ int   g_csrsrc[E_TOT];           // CSR: src node per slot
__device__ int   g_is64;                    // 1 if edge_index is int64, 0 if int32

// ---------------- edge dtype detection -------------------------------------
// Harness may deliver edge_index as int32 (its dtype list has no int64).
// Genuine int64 data: first 64 values all in [0, N_NODES). int32 data read as
// int64 packs two ids per word -> virtually certain to leave that range.
__global__ void detect_kernel(const void* ei) {
    const long long* e64 = (const long long*)ei;
    int ok = 1;
    for (int i = 0; i < 64; i++) {
        long long v = e64[i];
        if (v < 0 || v >= N_NODES) { ok = 0; break; }
    }
    g_is64 = ok;
}

__device__ __forceinline__ int edge_at(const void* ei, long long idx) {
    return g_is64 ? (int)((const long long*)ei)[idx]
                  : ((const int*)ei)[idx];
}

// ---------------- CSR build ------------------------------------------------
__global__ void deg_init_kernel() {
    int i = blockIdx.x * blockDim.x + threadIdx.x;
    if (i < N_NODES) g_deg[i] = 1;          // self loop
}

__global__ void deg_count_kernel(const void* ei) {
    int e = blockIdx.x * blockDim.x + threadIdx.x;
    if (e >= N_EDGES) return;
    atomicAdd(&g_deg[edge_at(ei, (long long)N_EDGES + e)], 1);
}

// single-block exclusive scan over 50k degrees -> rowptr (+ cursor copy)
__global__ void scan_kernel() {
    __shared__ int sums[1024];
    int t = threadIdx.x;
    const int CH = (N_NODES + 1023) / 1024;      // 49
    int beg = t * CH;
    int end = min(beg + CH, N_NODES);
    int s = 0;
    for (int i = beg; i < end; i++) s += g_deg[i];
    sums[t] = s;
    __syncthreads();
    for (int off = 1; off < 1024; off <<= 1) {   // Hillis-Steele inclusive
        int v = (t >= off) ? sums[t - off] : 0;
        __syncthreads();
        sums[t] += v;
        __syncthreads();
    }
    int run = (t == 0) ? 0 : sums[t - 1];        // exclusive prefix
    for (int i = beg; i < end; i++) {
        g_rowptr[i] = run;
        g_cursor[i] = run;
        run += g_deg[i];
    }
    if (t == 0) g_rowptr[N_NODES] = E_TOT;
}

__global__ void scatter_kernel(const void* ei) {
    int e = blockIdx.x * blockDim.x + threadIdx.x;
    if (e >= E_TOT) return;
    int s, d;
    if (e < N_EDGES) { s = edge_at(ei, e); d = edge_at(ei, (long long)N_EDGES + e); }
    else             { s = d = e - N_EDGES; }   // self loop
    int pos = atomicAdd(&g_cursor[d], 1);
    g_csrsrc[pos] = s;
}

// ---------------- tiled GEMM: g_h[M,64] = A[M,K] @ B[K,64] -----------------
// 64x64 block tile, 256 threads, 4x4 register micro-tile per thread.
// FROM_G2: A = g_h2 (layer 2); else A = Aarg (harness pointer, layer 1).
// Epilogue fuses the attention projections into g_as / g_at.
template<int K, bool FROM_G2>
__global__ void gemm64_kernel(const float* __restrict__ Aarg,
                              const float* __restrict__ B,
                              const float* __restrict__ aW,
                              const float* __restrict__ ab, int M) {
    const float* A = FROM_G2 ? (const float*)g_h2 : Aarg;
    constexpr int KC = (K > 64) ? 64 : K;        // K-chunk (shared <= 48KB)
    __shared__ __align__(16) float As[KC][64];
    __shared__ __align__(16) float Bs[K][64];
    int tid = threadIdx.x;
    int tx = tid & 15;            // col group (4 cols)
    int ty = tid >> 4;            // row group (4 rows)
    int row0 = blockIdx.x * 64;

    // load all of B (K x 64, contiguous) vectorized
    for (int i = tid; i < K * 16; i += 256)
        ((float4*)Bs)[i] = ((const float4*)B)[i];

    float acc[4][4];
#pragma unroll
    for (int i = 0; i < 4; i++)
#pragma unroll
        for (int j = 0; j < 4; j++) acc[i][j] = 0.0f;

    for (int kc = 0; kc < K; kc += KC) {
        // load A chunk transposed: As[k][row]; lanes span rows -> STS conflict-free
        for (int idx = tid; idx < 64 * (KC / 4); idx += 256) {
            int row = idx & 63;
            int kq  = idx >> 6;
            int grow = min(row0 + row, M - 1);
            float4 av = *(const float4*)(A + (size_t)grow * K + kc + kq * 4);
            As[kq * 4 + 0][row] = av.x;
            As[kq * 4 + 1][row] = av.y;
            As[kq * 4 + 2][row] = av.z;
            As[kq * 4 + 3][row] = av.w;
        }
        __syncthreads();
#pragma unroll 8
        for (int k = 0; k < KC; k++) {
            float4 a4 = *(float4*)&As[k][ty * 4];
            float4 b4 = *(float4*)&Bs[kc + k][tx * 4];
            float av[4] = {a4.x, a4.y, a4.z, a4.w};
            float bv[4] = {b4.x, b4.y, b4.z, b4.w};
#pragma unroll
            for (int i = 0; i < 4; i++)
#pragma unroll
                for (int j = 0; j < 4; j++)
                    acc[i][j] = fmaf(av[i], bv[j], acc[i][j]);
        }
        __syncthreads();
    }

    // epilogue: store g_h rows + fused alpha projections
    float4 ws = *(const float4*)(aW + tx * 4);           // aW[:64] slice
    float4 wt = *(const float4*)(aW + 64 + tx * 4);      // aW[64:] slice
    float abv = ab[0];
#pragma unroll
    for (int i = 0; i < 4; i++) {
        int row = row0 + ty * 4 + i;
        float s = fmaf(acc[i][0], ws.x, fmaf(acc[i][1], ws.y,
                  fmaf(acc[i][2], ws.z, acc[i][3] * ws.w)));
        float t = fmaf(acc[i][0], wt.x, fmaf(acc[i][1], wt.y,
                  fmaf(acc[i][2], wt.z, acc[i][3] * wt.w)));
#pragma unroll
        for (int o = 1; o < 16; o <<= 1) {               // reduce 16-lane tx group
            s += __shfl_xor_sync(0xffffffffu, s, o);
            t += __shfl_xor_sync(0xffffffffu, t, o);
        }
        if (row < M) {
            *(float4*)(g_h + (size_t)row * 64 + tx * 4) =
                make_float4(acc[i][0], acc[i][1], acc[i][2], acc[i][3]);
            if (tx == 0) { g_as[row] = s; g_at[row] = t + abv; }
        }
    }
}

// ---------------- head GEMM: out[M,NC] = g_h2[M,K] @ B[K,NC] + bias --------
template<int K, int NC>
__global__ void gemm_head_kernel(const float* __restrict__ B,
                                 const float* __restrict__ bias,
                                 float* __restrict__ C, int M) {
    __shared__ float Bs[K * NC];
    int tid = threadIdx.y * blockDim.x + threadIdx.x;
    int nth = blockDim.x * blockDim.y;
    for (int i = tid; i < K * NC; i += nth) Bs[i] = B[i];
    __syncthreads();
    int row = blockIdx.x * blockDim.y + threadIdx.y;
    if (row >= M) return;
    int col = threadIdx.x;
    const float* a = g_h2 + (size_t)row * K;
    float acc = bias[col];
#pragma unroll 16
    for (int k = 0; k < K; k++) acc = fmaf(a[k], Bs[k * NC + col], acc);
    C[(size_t)row * NC + col] = acc;
}

// ---------------- fused softmax + scatter-max aggregation ------------------
// one warp per dst node; no atomics. reads g_h -> writes g_h2.
// pass A: online softmax (m,z one pass; finite NEG_BIG avoids NaN in merge).
// pass C: half-warp per edge, float4 lanes; normalized weight computed inline.
__global__ void gat_layer_kernel(const float* __restrict__ bias) {
    int node = (blockIdx.x * blockDim.x + threadIdx.x) >> 5;
    int lane = threadIdx.x & 31;
    if (node >= N_NODES) return;
    int beg = g_rowptr[node], end = g_rowptr[node + 1];
    float atd = g_at[node];

    // pass A: sim = leaky_relu(as[src] + at[dst] + ab); online (m, z)
    float m = NEG_BIG, z = 0.0f;
    for (int i = beg + lane; i < end; i += 32) {
        float v = g_as[g_csrsrc[i]] + atd;
        v = (v < 0.0f) ? 0.2f * v : v;
        g_sim[i] = v;
        if (v > m) { z = fmaf(z, __expf(m - v), 1.0f); m = v; }
        else       { z += __expf(v - m); }
    }
    // warp-merge (m, z) pairs; all m finite -> no NaN from m - M
#pragma unroll
    for (int o = 16; o; o >>= 1) {
        float mo = __shfl_xor_sync(0xffffffffu, m, o);
        float zo = __shfl_xor_sync(0xffffffffu, z, o);
        float M  = fmaxf(m, mo);
        z = z * __expf(m - M) + zo * __expf(mo - M);   // empty lane: z=0 anyway
        m = M;
    }
    float invz = 1.0f / z;

    // pass C: acc = max_j softmax_j * g_h[src_j][:]
    // half-warp per edge: lanes 0-15 edge j, lanes 16-31 edge j+1; LDG.128 rows.
    int half = lane >> 4, l16 = lane & 15;
    float4 acc = make_float4(-INFINITY, -INFINITY, -INFINITY, -INFINITY);
    int j = beg + half;
    if (j < end) {
        float a = __expf(g_sim[j] - m) * invz;
        float4 xv = *(const float4*)(g_h + (size_t)g_csrsrc[j] * D_HID + l16 * 4);
        for (j += 2; j < end; j += 2) {
            float an = __expf(g_sim[j] - m) * invz;    // prefetch next pair
            float4 xn = *(const float4*)(g_h + (size_t)g_csrsrc[j] * D_HID + l16 * 4);
            acc.x = fmaxf(acc.x, a * xv.x);
            acc.y = fmaxf(acc.y, a * xv.y);
            acc.z = fmaxf(acc.z, a * xv.z);
            acc.w = fmaxf(acc.w, a * xv.w);
            a = an; xv = xn;
        }
        acc.x = fmaxf(acc.x, a * xv.x);
        acc.y = fmaxf(acc.y, a * xv.y);
        acc.z = fmaxf(acc.z, a * xv.z);
        acc.w = fmaxf(acc.w, a * xv.w);
    }
    // merge the two half-warp accumulators (all lanes participate;
    // fmaxf with -INF from an empty half is safe, never NaN)
    acc.x = fmaxf(acc.x, __shfl_xor_sync(0xffffffffu, acc.x, 16));
    acc.y = fmaxf(acc.y, __shfl_xor_sync(0xffffffffu, acc.y, 16));
    acc.z = fmaxf(acc.z, __shfl_xor_sync(0xffffffffu, acc.z, 16));
    acc.w = fmaxf(acc.w, __shfl_xor_sync(0xffffffffu, acc.w, 16));

    if (half == 0) {
        float4 b = *(const float4*)(bias + l16 * 4);
        float4 v;
        v.x = fmaxf(acc.x + b.x, 0.0f);
        v.y = fmaxf(acc.y + b.y, 0.0f);
        v.z = fmaxf(acc.z + b.z, 0.0f);
        v.w = fmaxf(acc.w + b.w, 0.0f);
        *(float4*)(g_h2 + (size_t)node * D_HID + l16 * 4) = v;
    }
}

// ---------------- in-place log_softmax over 40 classes (warp per node) -----
__global__ void lsm_kernel(float* __restrict__ logits) {
    int w    = (blockIdx.x * blockDim.x + threadIdx.x) >> 5;
    int lane = threadIdx.x & 31;
    if (w >= N_NODES) return;
    float* r = logits + (size_t)w * N_CLS;
    float v0 = r[lane];
    float v1 = (lane < N_CLS - 32) ? r[lane + 32] : NEG_BIG;
    float m = fmaxf(v0, v1);
#pragma unroll
    for (int o = 16; o; o >>= 1) m = fmaxf(m, __shfl_xor_sync(0xffffffffu, m, o));
    float sum = __expf(v0 - m) + ((lane < N_CLS - 32) ? __expf(v1 - m) : 0.0f);
#pragma unroll
    for (int o = 16; o; o >>= 1) sum += __shfl_xor_sync(0xffffffffu, sum, o);
    float ls = m + __logf(sum);
    r[lane] = v0 - ls;
    if (lane < N_CLS - 32) r[lane + 32] = v1 - ls;
}

// ---------------------------------------------------------------------------
extern "C" void kernel_launch(void* const* d_in, const int* in_sizes, int n_in,
                              void* d_out, int out_size) {
    const float* x   = (const float*)d_in[0];
    const void*  ei  = d_in[1];                 // int32 or int64; detected on device
    const float* W1  = (const float*)d_in[2];
    const float* aW1 = (const float*)d_in[3];
    const float* ab1 = (const float*)d_in[4];
    const float* b1  = (const float*)d_in[5];
    const float* W2  = (const float*)d_in[6];
    const float* aW2 = (const float*)d_in[7];
    const float* ab2 = (const float*)d_in[8];
    const float* b2  = (const float*)d_in[9];
    const float* Wo  = (const float*)d_in[10];
    const float* bo  = (const float*)d_in[11];
    float*       out = (float*)d_out;

    const int BLK = 256;
    int grid_node  = (N_NODES + BLK - 1) / BLK;
    int grid_edgeR = (N_EDGES + BLK - 1) / BLK;
    int grid_edgeT = (E_TOT + BLK - 1) / BLK;
    int grid_nwarp = (N_NODES * 32 + BLK - 1) / BLK;
    int grid_gemm  = (N_NODES + 63) / 64;

    // ---------------- CSR build (once; reused by both layers) ----------------
    detect_kernel   <<<1, 1>>>(ei);
    deg_init_kernel <<<grid_node,  BLK>>>();
    deg_count_kernel<<<grid_edgeR, BLK>>>(ei);
    scan_kernel     <<<1, 1024>>>();
    scatter_kernel  <<<grid_edgeT, BLK>>>(ei);

    // ---------------- layer 1: x -> g_h -> g_h2 ----------------
    gemm64_kernel<D_IN, false><<<grid_gemm, 256>>>(x, W1, aW1, ab1, N_NODES);
    gat_layer_kernel<<<grid_nwarp, BLK>>>(b1);

    // ---------------- layer 2: g_h2 -> g_h -> g_h2 ----------------
    gemm64_kernel<D_HID, true><<<grid_gemm, 256>>>(nullptr, W2, aW2, ab2, N_NODES);
    gat_layer_kernel<<<grid_nwarp, BLK>>>(b2);

    // ---------------- output head: g_h2 -> out ----------------
    {
        dim3 bd(N_CLS, 6);
        gemm_head_kernel<D_HID, N_CLS><<<(N_NODES + 5) / 6, bd>>>(Wo, bo, out, N_NODES);
    }
    lsm_kernel<<<grid_nwarp, BLK>>>(out);
}

// round 12
// speedup vs baseline: 1.3616x; 1.3616x over previous
#include <cuda_runtime.h>
#include <math.h>

#define N_NODES 50000
#define N_EDGES 800000
#define E_TOT   850000   // edges + self loops
#define D_IN    128
#define D_HID   64
#define N_CLS   40

#define NEG_BIG (-1.0e30f)   // finite "-inf" sentinel: exp(NEG_BIG - x) == 0, no NaN

#define SCAN_BLK 256
#define N_SBLK ((N_NODES + SCAN_BLK - 1) / SCAN_BLK)   // 196

// ---------------- scratch (static __device__ globals; no allocs) ------------
__device__ float g_h   [N_NODES * D_HID];   // GEMM output / GAT input
__device__ float g_h2  [N_NODES * D_HID];   // GAT output / next GEMM input
__device__ float g_sim [E_TOT];             // per-CSR-slot leaky-relu score
__device__ float g_as  [N_NODES];           // h . aW[:D]
__device__ float g_at  [N_NODES];           // h . aW[D:] + ab
__device__ int   g_deg [N_NODES];           // in-degree (incl self loop)
__device__ int   g_rowptr[N_NODES + 1];     // CSR row pointers (by dst)
__device__ int   g_cursor[N_NODES];         // scatter cursors
__device__ int   g_csrsrc[E_TOT];           // CSR: src node per slot
__device__ int   g_psum[N_SBLK];            // per-block degree partial sums
__device__ int   g_is64;                    // 1 if edge_index is int64, 0 if int32

// ---------------- edge dtype detection (1 warp, ballot) ---------------------
__global__ void detect_kernel(const void* ei) {
    const long long* e64 = (const long long*)ei;
    int t = threadIdx.x;
    long long v0 = e64[t], v1 = e64[t + 32];
    int bad = (v0 < 0 || v0 >= N_NODES) || (v1 < 0 || v1 >= N_NODES);
    unsigned mask = __ballot_sync(0xffffffffu, bad);
    if (t == 0) g_is64 = (mask == 0u);
}

__device__ __forceinline__ int edge_at(const void* ei, long long idx) {
    return g_is64 ? (int)((const long long*)ei)[idx]
                  : ((const int*)ei)[idx];
}

// ---------------- CSR build ------------------------------------------------
__global__ void deg_init_kernel() {
    int i = blockIdx.x * blockDim.x + threadIdx.x;
    if (i < N_NODES) g_deg[i] = 1;          // self loop
}

__global__ void deg_count_kernel(const void* ei) {
    int e = blockIdx.x * blockDim.x + threadIdx.x;
    if (e >= N_EDGES) return;
    atomicAdd(&g_deg[edge_at(ei, (long long)N_EDGES + e)], 1);
}

// 3-phase full-chip exclusive scan over g_deg -> g_rowptr / g_cursor
__global__ void scan_phase1() {            // grid = N_SBLK
    __shared__ int sh[SCAN_BLK];
    int i = blockIdx.x * SCAN_BLK + threadIdx.x;
    sh[threadIdx.x] = (i < N_NODES) ? g_deg[i] : 0;
    __syncthreads();
    for (int off = SCAN_BLK / 2; off; off >>= 1) {
        if (threadIdx.x < off) sh[threadIdx.x] += sh[threadIdx.x + off];
        __syncthreads();
    }
    if (threadIdx.x == 0) g_psum[blockIdx.x] = sh[0];
}

__global__ void scan_phase2() {            // 1 block
    __shared__ int sh[SCAN_BLK];
    int t = threadIdx.x;
    sh[t] = (t < N_SBLK) ? g_psum[t] : 0;
    __syncthreads();
    for (int off = 1; off < SCAN_BLK; off <<= 1) {  // Hillis-Steele inclusive
        int v = (t >= off) ? sh[t - off] : 0;
        __syncthreads();
        sh[t] += v;
        __syncthreads();
    }
    if (t < N_SBLK) g_psum[t] = (t == 0) ? 0 : sh[t - 1];   // exclusive
}

__global__ void scan_phase3() {            // grid = N_SBLK
    __shared__ int sh[SCAN_BLK];
    int t = threadIdx.x;
    int i = blockIdx.x * SCAN_BLK + t;
    int v = (i < N_NODES) ? g_deg[i] : 0;
    sh[t] = v;
    __syncthreads();
    for (int off = 1; off < SCAN_BLK; off <<= 1) {  // Hillis-Steele inclusive
        int u = (t >= off) ? sh[t - off] : 0;
        __syncthreads();
        sh[t] += u;
        __syncthreads();
    }
    int excl = g_psum[blockIdx.x] + sh[t] - v;      // exclusive prefix
    if (i < N_NODES) { g_rowptr[i] = excl; g_cursor[i] = excl; }
    if (i == N_NODES - 1) g_rowptr[N_NODES] = E_TOT;
}

__global__ void scatter_kernel(const void* ei) {
    int e = blockIdx.x * blockDim.x + threadIdx.x;
    if (e >= E_TOT) return;
    int s, d;
    if (e < N_EDGES) { s = edge_at(ei, e); d = edge_at(ei, (long long)N_EDGES + e); }
    else             { s = d = e - N_EDGES; }   // self loop
    int pos = atomicAdd(&g_cursor[d], 1);
    g_csrsrc[pos] = s;
}

// ---------------- tiled GEMM: g_h[M,64] = A[M,K] @ B[K,64] -----------------
// 64x64 block tile, 256 threads, 4x4 register micro-tile per thread.
// FROM_G2: A = g_h2 (layer 2); else A = Aarg (harness pointer, layer 1).
// Epilogue fuses the attention projections into g_as / g_at.
template<int K, bool FROM_G2>
__global__ void gemm64_kernel(const float* __restrict__ Aarg,
                              const float* __restrict__ B,
                              const float* __restrict__ aW,
                              const float* __restrict__ ab, int M) {
    const float* A = FROM_G2 ? (const float*)g_h2 : Aarg;
    constexpr int KC = (K > 64) ? 64 : K;        // K-chunk (shared <= 48KB)
    __shared__ __align__(16) float As[KC][64];
    __shared__ __align__(16) float Bs[K][64];
    int tid = threadIdx.x;
    int tx = tid & 15;            // col group (4 cols)
    int ty = tid >> 4;            // row group (4 rows)
    int row0 = blockIdx.x * 64;

    // load all of B (K x 64, contiguous) vectorized
    for (int i = tid; i < K * 16; i += 256)
        ((float4*)Bs)[i] = ((const float4*)B)[i];

    float acc[4][4];
#pragma unroll
    for (int i = 0; i < 4; i++)
#pragma unroll
        for (int j = 0; j < 4; j++) acc[i][j] = 0.0f;

    for (int kc = 0; kc < K; kc += KC) {
        // load A chunk transposed: As[k][row]; lanes span rows -> STS conflict-free
        for (int idx = tid; idx < 64 * (KC / 4); idx += 256) {
            int row = idx & 63;
            int kq  = idx >> 6;
            int grow = min(row0 + row, M - 1);
            float4 av = *(const float4*)(A + (size_t)grow * K + kc + kq * 4);
            As[kq * 4 + 0][row] = av.x;
            As[kq * 4 + 1][row] = av.y;
            As[kq * 4 + 2][row] = av.z;
            As[kq * 4 + 3][row] = av.w;
        }
        __syncthreads();
#pragma unroll 8
        for (int k = 0; k < KC; k++) {
            float4 a4 = *(float4*)&As[k][ty * 4];
            float4 b4 = *(float4*)&Bs[kc + k][tx * 4];
            float av[4] = {a4.x, a4.y, a4.z, a4.w};
            float bv[4] = {b4.x, b4.y, b4.z, b4.w};
#pragma unroll
            for (int i = 0; i < 4; i++)
#pragma unroll
                for (int j = 0; j < 4; j++)
                    acc[i][j] = fmaf(av[i], bv[j], acc[i][j]);
        }
        __syncthreads();
    }

    // epilogue: store g_h rows + fused alpha projections
    float4 ws = *(const float4*)(aW + tx * 4);           // aW[:64] slice
    float4 wt = *(const float4*)(aW + 64 + tx * 4);      // aW[64:] slice
    float abv = ab[0];
#pragma unroll
    for (int i = 0; i < 4; i++) {
        int row = row0 + ty * 4 + i;
        float s = fmaf(acc[i][0], ws.x, fmaf(acc[i][1], ws.y,
                  fmaf(acc[i][2], ws.z, acc[i][3] * ws.w)));
        float t = fmaf(acc[i][0], wt.x, fmaf(acc[i][1], wt.y,
                  fmaf(acc[i][2], wt.z, acc[i][3] * wt.w)));
#pragma unroll
        for (int o = 1; o < 16; o <<= 1) {               // reduce 16-lane tx group
            s += __shfl_xor_sync(0xffffffffu, s, o);
            t += __shfl_xor_sync(0xffffffffu, t, o);
        }
        if (row < M) {
            *(float4*)(g_h + (size_t)row * 64 + tx * 4) =
                make_float4(acc[i][0], acc[i][1], acc[i][2], acc[i][3]);
            if (tx == 0) { g_as[row] = s; g_at[row] = t + abv; }
        }
    }
}

// ---------------- head GEMM: out[M,NC] = g_h2[M,K] @ B[K,NC] + bias --------
template<int K, int NC>
__global__ void gemm_head_kernel(const float* __restrict__ B,
                                 const float* __restrict__ bias,
                                 float* __restrict__ C, int M) {
    __shared__ float Bs[K * NC];
    int tid = threadIdx.y * blockDim.x + threadIdx.x;
    int nth = blockDim.x * blockDim.y;
    for (int i = tid; i < K * NC; i += nth) Bs[i] = B[i];
    __syncthreads();
    int row = blockIdx.x * blockDim.y + threadIdx.y;
    if (row >= M) return;
    int col = threadIdx.x;
    const float* a = g_h2 + (size_t)row * K;
    float acc = bias[col];
#pragma unroll 16
    for (int k = 0; k < K; k++) acc = fmaf(a[k], Bs[k * NC + col], acc);
    C[(size_t)row * NC + col] = acc;
}

// ---------------- fused softmax + scatter-max aggregation ------------------
// one warp per dst node; no atomics. reads g_h -> writes g_h2.
// pass A: online softmax (m,z one pass; finite NEG_BIG avoids NaN in merge).
// pass C: half-warp per edge, float4 lanes; normalized weight computed inline.
__global__ void gat_layer_kernel(const float* __restrict__ bias) {
    int node = (blockIdx.x * blockDim.x + threadIdx.x) >> 5;
    int lane = threadIdx.x & 31;
    if (node >= N_NODES) return;
    int beg = g_rowptr[node], end = g_rowptr[node + 1];
    float atd = g_at[node];

    // pass A: sim = leaky_relu(as[src] + at[dst] + ab); online (m, z)
    float m = NEG_BIG, z = 0.0f;
    for (int i = beg + lane; i < end; i += 32) {
        float v = g_as[g_csrsrc[i]] + atd;
        v = (v < 0.0f) ? 0.2f * v : v;
        g_sim[i] = v;
        if (v > m) { z = fmaf(z, __expf(m - v), 1.0f); m = v; }
        else       { z += __expf(v - m); }
    }
    // warp-merge (m, z) pairs; all m finite -> no NaN from m - M
#pragma unroll
    for (int o = 16; o; o >>= 1) {
        float mo = __shfl_xor_sync(0xffffffffu, m, o);
        float zo = __shfl_xor_sync(0xffffffffu, z, o);
        float M  = fmaxf(m, mo);
        z = z * __expf(m - M) + zo * __expf(mo - M);   // empty lane: z=0 anyway
        m = M;
    }
    float invz = 1.0f / z;

    // pass C: acc = max_j softmax_j * g_h[src_j][:]
    // half-warp per edge: lanes 0-15 edge j, lanes 16-31 edge j+1; LDG.128 rows.
    int half = lane >> 4, l16 = lane & 15;
    float4 acc = make_float4(-INFINITY, -INFINITY, -INFINITY, -INFINITY);
    int j = beg + half;
    if (j < end) {
        float a = __expf(g_sim[j] - m) * invz;
        float4 xv = *(const float4*)(g_h + (size_t)g_csrsrc[j] * D_HID + l16 * 4);
        for (j += 2; j < end; j += 2) {
            float an = __expf(g_sim[j] - m) * invz;    // prefetch next pair
            float4 xn = *(const float4*)(g_h + (size_t)g_csrsrc[j] * D_HID + l16 * 4);
            acc.x = fmaxf(acc.x, a * xv.x);
            acc.y = fmaxf(acc.y, a * xv.y);
            acc.z = fmaxf(acc.z, a * xv.z);
            acc.w = fmaxf(acc.w, a * xv.w);
            a = an; xv = xn;
        }
        acc.x = fmaxf(acc.x, a * xv.x);
        acc.y = fmaxf(acc.y, a * xv.y);
        acc.z = fmaxf(acc.z, a * xv.z);
        acc.w = fmaxf(acc.w, a * xv.w);
    }
    // merge the two half-warp accumulators (all lanes participate;
    // fmaxf with -INF from an empty half is safe, never NaN)
    acc.x = fmaxf(acc.x, __shfl_xor_sync(0xffffffffu, acc.x, 16));
    acc.y = fmaxf(acc.y, __shfl_xor_sync(0xffffffffu, acc.y, 16));
    acc.z = fmaxf(acc.z, __shfl_xor_sync(0xffffffffu, acc.z, 16));
    acc.w = fmaxf(acc.w, __shfl_xor_sync(0xffffffffu, acc.w, 16));

    if (half == 0) {
        float4 b = *(const float4*)(bias + l16 * 4);
        float4 v;
        v.x = fmaxf(acc.x + b.x, 0.0f);
        v.y = fmaxf(acc.y + b.y, 0.0f);
        v.z = fmaxf(acc.z + b.z, 0.0f);
        v.w = fmaxf(acc.w + b.w, 0.0f);
        *(float4*)(g_h2 + (size_t)node * D_HID + l16 * 4) = v;
    }
}

// ---------------- in-place log_softmax over 40 classes (warp per node) -----
__global__ void lsm_kernel(float* __restrict__ logits) {
    int w    = (blockIdx.x * blockDim.x + threadIdx.x) >> 5;
    int lane = threadIdx.x & 31;
    if (w >= N_NODES) return;
    float* r = logits + (size_t)w * N_CLS;
    float v0 = r[lane];
    float v1 = (lane < N_CLS - 32) ? r[lane + 32] : NEG_BIG;
    float m = fmaxf(v0, v1);
#pragma unroll
    for (int o = 16; o; o >>= 1) m = fmaxf(m, __shfl_xor_sync(0xffffffffu, m, o));
    float sum = __expf(v0 - m) + ((lane < N_CLS - 32) ? __expf(v1 - m) : 0.0f);
#pragma unroll
    for (int o = 16; o; o >>= 1) sum += __shfl_xor_sync(0xffffffffu, sum, o);
    float ls = m + __logf(sum);
    r[lane] = v0 - ls;
    if (lane < N_CLS - 32) r[lane + 32] = v1 - ls;
}

// ---------------------------------------------------------------------------
extern "C" void kernel_launch(void* const* d_in, const int* in_sizes, int n_in,
                              void* d_out, int out_size) {
    const float* x   = (const float*)d_in[0];
    const void*  ei  = d_in[1];                 // int32 or int64; detected on device
    const float* W1  = (const float*)d_in[2];
    const float* aW1 = (const float*)d_in[3];
    const float* ab1 = (const float*)d_in[4];
    const float* b1  = (const float*)d_in[5];
    const float* W2  = (const float*)d_in[6];
    const float* aW2 = (const float*)d_in[7];
    const float* ab2 = (const float*)d_in[8];
    const float* b2  = (const float*)d_in[9];
    const float* Wo  = (const float*)d_in[10];
    const float* bo  = (const float*)d_in[11];
    float*       out = (float*)d_out;

    const int BLK = 256;
    int grid_node  = (N_NODES + BLK - 1) / BLK;
    int grid_edgeR = (N_EDGES + BLK - 1) / BLK;
    int grid_edgeT = (E_TOT + BLK - 1) / BLK;
    int grid_nwarp = (N_NODES * 32 + BLK - 1) / BLK;
    int grid_gemm  = (N_NODES + 63) / 64;

    // ---------------- CSR build (once; reused by both layers) ----------------
    detect_kernel   <<<1, 32>>>(ei);
    deg_init_kernel <<<grid_node,  BLK>>>();
    deg_count_kernel<<<grid_edgeR, BLK>>>(ei);
    scan_phase1     <<<N_SBLK, SCAN_BLK>>>();
    scan_phase2     <<<1, SCAN_BLK>>>();
    scan_phase3     <<<N_SBLK, SCAN_BLK>>>();
    scatter_kernel  <<<grid_edgeT, BLK>>>(ei);

    // ---------------- layer 1: x -> g_h -> g_h2 ----------------
    gemm64_kernel<D_IN, false><<<grid_gemm, 256>>>(x, W1, aW1, ab1, N_NODES);
    gat_layer_kernel<<<grid_nwarp, BLK>>>(b1);

    // ---------------- layer 2: g_h2 -> g_h -> g_h2 ----------------
    gemm64_kernel<D_HID, true><<<grid_gemm, 256>>>(nullptr, W2, aW2, ab2, N_NODES);
    gat_layer_kernel<<<grid_nwarp, BLK>>>(b2);

    // ---------------- output head: g_h2 -> out ----------------
    {
        dim3 bd(N_CLS, 6);
        gemm_head_kernel<D_HID, N_CLS><<<(N_NODES + 5) / 6, bd>>>(Wo, bo, out, N_NODES);
    }
    lsm_kernel<<<grid_nwarp, BLK>>>(out);
}